// round 16
// baseline (speedup 1.0000x reference)
#include <cuda_runtime.h>
#include <cuda_fp16.h>
#include <cstdint>

// ---------------------------------------------------------------------------
// GeneralizedBilinearAttention via mma.sync fp16 (base sm_103 ISA).
//   pre_a: AO rows (lina + AOh fp16, 8-row loop/warp) + W->WTh + mask
//   g1x  : aM = AOh @ WTh^T (64x128 tiles, 1 product) + co-scheduled IN rows
//   g23  : sim = INh @ aMh^T (1 product) -> tanh/masked-softmax -> attn(smem)
//          -> out = attn @ AOh (B via ldmatrix.trans), fully fused
// fp32 acc. K32 chunks, 3-stage cp.async pipelines. Raw fp32 inputs read
// with streaming (.cs) hints — they are single-use.
// ---------------------------------------------------------------------------

#define CB 128
#define CT 256
#define CN 128
#define CAD 512
#define CVD 512

__device__ __align__(16) unsigned short g_AOh[CB * CN * CAD];
__device__ __align__(16) unsigned short g_INh[CB * CT * CVD];
__device__ __align__(16) unsigned short g_WTh[CVD * CAD];
__device__ __align__(16) unsigned short g_aMh[CB * CN * CVD];
__device__ __align__(16) float g_lina[CB * CN];
__device__ __align__(16) float g_linb[CB * CT];
__device__ __align__(16) float g_maskf[CB * CN];

// ---- smem layouts -------------------------------------------------------------
#define TILEB 8192
// g1: A 64x32 (4KB) + B 128x32 (8KB)
#define G1_A   0
#define G1_B   4096
#define STAGE1 12288
#define SMEM_G1 (3 * STAGE1)
// g23 phase 1: A, Bh (8KB each) = 16KB/stage, 3 stages = 48KB
#define SM_T0 0
#define SM_T1 TILEB
#define STAGE2 (2 * TILEB)
// g23 phase 2 overlay: attn 4x8KB at 0, B stages at 32KB (3x8KB)
#define PH2_ATT 0
#define PH2_B   32768
#define SM_LIN  57344
#define SM_MSK (SM_LIN + 512)
#define SM_LNB (SM_MSK + 512)
#define SM_RED (SM_LNB + 512)
#define SMEM_G23 (SM_RED + 2048)     // 60928

__device__ __forceinline__ uint32_t smem_u32(const void* p) {
    return (uint32_t)__cvta_generic_to_shared(p);
}
__device__ __forceinline__ uint32_t swz(int row, int c16) {
    return (uint32_t)(row * 64 + ((c16 ^ ((row >> 1) & 3)) << 4));
}
__device__ __forceinline__ uint32_t swzbt(int row, int c16) {
    return (uint32_t)(row * 256 + ((c16 ^ (row & 7)) << 4));
}
__device__ __forceinline__ void ldsm4(uint32_t* r, uint32_t addr) {
    asm volatile("ldmatrix.sync.aligned.m8n8.x4.shared.b16 {%0,%1,%2,%3}, [%4];"
                 : "=r"(r[0]), "=r"(r[1]), "=r"(r[2]), "=r"(r[3]) : "r"(addr));
}
__device__ __forceinline__ void ldsm4t(uint32_t* r, uint32_t addr) {
    asm volatile("ldmatrix.sync.aligned.m8n8.x4.trans.shared.b16 {%0,%1,%2,%3}, [%4];"
                 : "=r"(r[0]), "=r"(r[1]), "=r"(r[2]), "=r"(r[3]) : "r"(addr));
}
__device__ __forceinline__ void mma_f16(float* c, const uint32_t* a,
                                        uint32_t b0, uint32_t b1) {
    asm volatile("mma.sync.aligned.m16n8k16.row.col.f32.f16.f16.f32 "
                 "{%0,%1,%2,%3}, {%4,%5,%6,%7}, {%8,%9}, {%0,%1,%2,%3};"
                 : "+f"(c[0]), "+f"(c[1]), "+f"(c[2]), "+f"(c[3])
                 : "r"(a[0]), "r"(a[1]), "r"(a[2]), "r"(a[3]), "r"(b0), "r"(b1));
}
__device__ __forceinline__ void cpa(uint32_t d, const void* g) {
    asm volatile("cp.async.cg.shared.global [%0], [%1], 16;"
                 :: "r"(d), "l"(g) : "memory");
}
__device__ __forceinline__ uint32_t pack2h(float x, float y) {
    __half2 h = __floats2half2_rn(x, y);
    return *(uint32_t*)&h;
}
// streaming fp32x4 load (single-use raw inputs)
__device__ __forceinline__ float4 ldcs4(const float* p) {
    return __ldcs((const float4*)p);
}

// ---------------------------------------------------------------------------
// pre_a: AO rows [256 blks x 8 warps x 8-row loop] + W->WTh [256] + mask [1].
// (8-row serial loop per warp = measured-best shape: 14.3us.)
// ---------------------------------------------------------------------------
#define PA_LIN 256
#define PA_WT  256
__global__ void __launch_bounds__(256) pre_a(
    const float* __restrict__ AO, const float* __restrict__ a_w,
    const float* __restrict__ W, const unsigned char* __restrict__ m) {
    const int bid = blockIdx.x;
    const int tid = threadIdx.x;
    if (bid < PA_LIN) {
        const int idx = bid * 8 + (tid >> 5);
        const int lane = tid & 31;
        for (int rr = 0; rr < 8; ++rr) {
            const int r = idx + rr * 2048;
            const float* row = AO + (size_t)r * CAD;
            uint2* dst = (uint2*)g_AOh + (size_t)r * 128;
            float s = 0.f;
#pragma unroll
            for (int k = 0; k < 512; k += 128) {
                int e = k + lane * 4;
                float4 x = ldcs4(row + e);
                float4 y = *(const float4*)(a_w + e);
                s += x.x * y.x + x.y * y.y + x.z * y.z + x.w * y.w;
                dst[e >> 2] = make_uint2(pack2h(x.x, x.y), pack2h(x.z, x.w));
            }
#pragma unroll
            for (int o = 16; o; o >>= 1) s += __shfl_xor_sync(0xffffffffu, s, o);
            if (lane == 0) g_lina[r] = s;
        }
    } else if (bid < PA_LIN + PA_WT) {
        __shared__ float t[32][33];
        const int idx = bid - PA_LIN;
        const int v0 = (idx & 15) * 32, a0 = (idx >> 4) * 32;
        const int tx = tid & 31, ty = tid >> 5;
        for (int i = ty; i < 32; i += 8)
            t[i][tx] = W[(size_t)(a0 + i) * CVD + v0 + tx];
        __syncthreads();
        for (int i = ty; i < 32; i += 8)
            g_WTh[(size_t)(v0 + i) * CAD + a0 + tx] =
                __half_as_ushort(__float2half_rn(t[tx][i]));
    } else {
        __shared__ int s_notbin, s_odd;
        if (tid == 0) { s_notbin = 0; s_odd = 0; }
        __syncthreads();
        int notbin = 0, odd = 0;
        for (int i = tid; i < CB * CN; i += 256) {
            unsigned char v = m[i];
            if (v > 1) notbin = 1;
            if ((i & 3) && v == 1) odd = 1;
        }
        if (notbin) atomicOr(&s_notbin, 1);
        if (odd)    atomicOr(&s_odd, 1);
        __syncthreads();
        const int md = s_notbin ? 2 : (s_odd ? 0 : 1);
        for (int i = tid; i < CB * CN; i += 256) {
            float v;
            if (md == 0)      v = (m[i] != 0) ? 1.f : 0.f;
            else if (md == 1) v = (((const int*)(const void*)m)[i] != 0) ? 1.f : 0.f;
            else              v = (((const float*)(const void*)m)[i] != 0.f) ? 1.f : 0.f;
            g_maskf[i] = v;
        }
    }
}

// ---------------------------------------------------------------------------
// g1x: grid (4+16, 256).
//   x <  4 : GEMM CTA — aM tile = AOh @ WTh^T (64x128, 1 product)
//   x >= 4 : IN-row CTA — linb + INh fp16 convert (1 row/warp)
// ---------------------------------------------------------------------------
__global__ void __launch_bounds__(256, 3) g1x(const float* __restrict__ IN,
                                              const float* __restrict__ b_w) {
    extern __shared__ char sm[];
    const int tid = threadIdx.x;
    if (blockIdx.x >= 4) {
        const int r = (((int)blockIdx.x - 4) + (int)blockIdx.y * 16) * 8 + (tid >> 5);
        const int lane = tid & 31;
        const float* row = IN + (size_t)r * CVD;
        uint2* dst = (uint2*)g_INh + (size_t)r * 128;
        float s = 0.f;
#pragma unroll
        for (int k = 0; k < 512; k += 128) {
            int e = k + lane * 4;
            float4 x = ldcs4(row + e);
            float4 y = *(const float4*)(b_w + e);
            s += x.x * y.x + x.y * y.y + x.z * y.z + x.w * y.w;
            dst[e >> 2] = make_uint2(pack2h(x.x, x.y), pack2h(x.z, x.w));
        }
#pragma unroll
        for (int o = 16; o; o >>= 1) s += __shfl_xor_sync(0xffffffffu, s, o);
        if (lane == 0) g_linb[r] = s;
        return;
    }

    const uint32_t smb = smem_u32(sm);
    const int lane = tid & 31, w = tid >> 5;
    const int n0 = blockIdx.x * 128;
    const size_t m0 = (size_t)blockIdx.y * 64;
    const int mw = (w & 1) * 32, nw = (w >> 1) * 32;
    const int grp = lane >> 3, rin = lane & 7;
    int rowm[2], rowb[2];
#pragma unroll
    for (int mi = 0; mi < 2; ++mi) rowm[mi] = mw + mi * 16 + rin + ((grp & 1) << 3);
#pragma unroll
    for (int j = 0; j < 2; ++j)    rowb[j] = nw + j * 16 + rin + ((grp & 1) << 3);
    const int cgrp = grp >> 1;

    float acc[2][4][4];
#pragma unroll
    for (int a = 0; a < 2; ++a)
#pragma unroll
        for (int b = 0; b < 4; ++b)
#pragma unroll
            for (int cc = 0; cc < 4; ++cc) acc[a][b][cc] = 0.f;

    const unsigned short* A = g_AOh + m0 * CAD;
    const unsigned short* B = g_WTh + (size_t)n0 * CAD;

    uint32_t doffA, doffB[2];
    const unsigned short *pA, *pB[2];
    {
        int rowA = tid >> 2, cA = tid & 3;
        doffA = swz(rowA, cA);
        pA = A + (size_t)rowA * CAD + cA * 8;
#pragma unroll
        for (int i = 0; i < 2; ++i) {
            int u = i * 256 + tid, row = u >> 2, c = u & 3;
            doffB[i] = swz(row, c);
            pB[i] = B + (size_t)row * CAD + c * 8;
        }
    }
#pragma unroll
    for (int s = 0; s < 2; ++s) {
        const uint32_t st = smb + (uint32_t)s * STAGE1;
        cpa(st + G1_A + doffA, pA); pA += 32;
#pragma unroll
        for (int i = 0; i < 2; ++i) {
            cpa(st + G1_B + doffB[i], pB[i]); pB[i] += 32;
        }
        asm volatile("cp.async.commit_group;" ::: "memory");
    }
    uint32_t stg = 0;
    const int nch = CAD >> 5;
    for (int c = 0; c < nch; ++c) {
        if (c == nch - 1) asm volatile("cp.async.wait_group 0;" ::: "memory");
        else              asm volatile("cp.async.wait_group 1;" ::: "memory");
        __syncthreads();
        if (c + 2 < nch) {
            uint32_t s2 = stg + 2; if (s2 >= 3) s2 -= 3;
            const uint32_t st2 = smb + s2 * STAGE1;
            cpa(st2 + G1_A + doffA, pA); pA += 32;
#pragma unroll
            for (int i = 0; i < 2; ++i) {
                cpa(st2 + G1_B + doffB[i], pB[i]); pB[i] += 32;
            }
            asm volatile("cp.async.commit_group;" ::: "memory");
        }
        const uint32_t st = smb + stg * STAGE1;
#pragma unroll
        for (int ks = 0; ks < 2; ++ks) {
            const int cu = 2 * ks + cgrp;
            uint32_t b0[4], b1[4], a0[4], a1[4];
            ldsm4(b0, st + G1_B + swz(rowb[0], cu));
            ldsm4(b1, st + G1_B + swz(rowb[1], cu));
            ldsm4(a0, st + G1_A + swz(rowm[0], cu));
            ldsm4(a1, st + G1_A + swz(rowm[1], cu));
#pragma unroll
            for (int nj = 0; nj < 4; ++nj) {
                const int o = nj & 1;
                const uint32_t* bb = (nj < 2) ? b0 : b1;
                mma_f16(acc[0][nj], a0, bb[o], bb[o + 2]);
                mma_f16(acc[1][nj], a1, bb[o], bb[o + 2]);
            }
        }
        if (++stg == 3) stg = 0;
    }

    const int qr = lane >> 2, qc = (lane & 3) * 2;
    uint32_t* ghi = (uint32_t*)g_aMh;
#pragma unroll
    for (int mi = 0; mi < 2; ++mi)
#pragma unroll
        for (int nj = 0; nj < 4; ++nj) {
            size_t r0 = m0 + mw + mi * 16 + qr;
            size_t cp = (size_t)(n0 + nw + nj * 8 + qc) >> 1;
            ghi[r0 * (CVD >> 1) + cp] =
                pack2h(acc[mi][nj][0], acc[mi][nj][1]);
            ghi[(r0 + 8) * (CVD >> 1) + cp] =
                pack2h(acc[mi][nj][2], acc[mi][nj][3]);
        }
}

// ---------------------------------------------------------------------------
// G23: sim = INh @ aMh^T (1 product) -> softmax -> attn(smem) -> out = attn @ AOh.
//      grid (2 Mtiles, B), 256 threads, 2 CTAs/SM.
// ---------------------------------------------------------------------------
__global__ void __launch_bounds__(256, 2) g23_mma(const float* __restrict__ biasp,
                                                  float* __restrict__ OUT) {
    extern __shared__ char sm[];
    const uint32_t smb = smem_u32(sm);
    const int tid = threadIdx.x;
    const int b = blockIdx.y;
    const int m0 = blockIdx.x * 128;
    float* sl  = (float*)(sm + SM_LIN);
    float* sk  = (float*)(sm + SM_MSK);
    float* slb = (float*)(sm + SM_LNB);
    float* red = (float*)(sm + SM_RED);
    if (tid < 128) {
        sl[tid]  = g_lina[b * CN + tid];
        sk[tid]  = g_maskf[b * CN + tid];
        slb[tid] = g_linb[b * CT + m0 + tid];
    }
    const int lane = tid & 31, w = tid >> 5;
    const int mw = (w & 1) * 64, nw = (w >> 1) * 32;
    const int grp = lane >> 3, rin = lane & 7;
    int rowm[4], rowb[2];
#pragma unroll
    for (int mi = 0; mi < 4; ++mi) rowm[mi] = mw + mi * 16 + rin + ((grp & 1) << 3);
#pragma unroll
    for (int j = 0; j < 2; ++j)    rowb[j] = nw + j * 16 + rin + ((grp & 1) << 3);
    const int cgrp = grp >> 1;

    float acc[4][4][4];
#pragma unroll
    for (int a = 0; a < 4; ++a)
#pragma unroll
        for (int bb = 0; bb < 4; ++bb)
#pragma unroll
            for (int cc = 0; cc < 4; ++cc) acc[a][bb][cc] = 0.f;

    // ---------------- phase 1: sim mainloop (1 product) ----------------
    const unsigned short* A  = g_INh + ((size_t)b * CT + m0) * CVD;
    const unsigned short* Bh = g_aMh + (size_t)b * CN * CVD;

    uint32_t doff[2];
    const unsigned short *pA[2], *pBh[2];
#pragma unroll
    for (int i = 0; i < 2; ++i) {
        int u = i * 256 + tid, row = u >> 2, c = u & 3;
        doff[i] = swz(row, c);
        pA[i]  = A  + (size_t)row * CVD + c * 8;
        pBh[i] = Bh + (size_t)row * CVD + c * 8;
    }
#pragma unroll
    for (int s = 0; s < 2; ++s) {
        const uint32_t st = smb + (uint32_t)s * STAGE2;
#pragma unroll
        for (int i = 0; i < 2; ++i) {
            cpa(st + SM_T0 + doff[i], pA[i]);
            cpa(st + SM_T1 + doff[i], pBh[i]);
            pA[i] += 32; pBh[i] += 32;
        }
        asm volatile("cp.async.commit_group;" ::: "memory");
    }
    uint32_t stg = 0;
    const int nch = CVD >> 5;
    for (int c = 0; c < nch; ++c) {
        if (c == nch - 1) asm volatile("cp.async.wait_group 0;" ::: "memory");
        else              asm volatile("cp.async.wait_group 1;" ::: "memory");
        __syncthreads();
        if (c + 2 < nch) {
            uint32_t s2 = stg + 2; if (s2 >= 3) s2 -= 3;
            const uint32_t st2 = smb + s2 * STAGE2;
#pragma unroll
            for (int i = 0; i < 2; ++i) {
                cpa(st2 + SM_T0 + doff[i], pA[i]);
                cpa(st2 + SM_T1 + doff[i], pBh[i]);
                pA[i] += 32; pBh[i] += 32;
            }
            asm volatile("cp.async.commit_group;" ::: "memory");
        }
        const uint32_t st = smb + stg * STAGE2;
#pragma unroll
        for (int ks = 0; ks < 2; ++ks) {
            const int cu = 2 * ks + cgrp;
            uint32_t bh[2][4];
#pragma unroll
            for (int j = 0; j < 2; ++j)
                ldsm4(bh[j], st + SM_T1 + swz(rowb[j], cu));
            uint32_t a2[2][4];
            ldsm4(a2[0], st + SM_T0 + swz(rowm[0], cu));
#pragma unroll
            for (int mi = 0; mi < 4; ++mi) {
                const int cur = mi & 1;
                if (mi < 3) ldsm4(a2[cur ^ 1], st + SM_T0 + swz(rowm[mi + 1], cu));
#pragma unroll
                for (int nj = 0; nj < 4; ++nj) {
                    const int j = nj >> 1, o = nj & 1;
                    mma_f16(acc[mi][nj], a2[cur], bh[j][o], bh[j][o + 2]);
                }
            }
        }
        if (++stg == 3) stg = 0;
    }
    __syncthreads();

    // ---- phase-2 B preloads (overlap with softmax epilogue) ----
    uint32_t doffB2[2];
    const unsigned short* pB2[2];
#pragma unroll
    for (int i = 0; i < 2; ++i) {
        int u = i * 256 + tid;
        int rowB = u >> 4, cB = u & 15;
        doffB2[i] = swzbt(rowB, cB);
        pB2[i] = g_AOh + (size_t)b * CN * CAD + (size_t)rowB * CAD + cB * 8;
    }
#pragma unroll
    for (int s = 0; s < 2; ++s) {
        const uint32_t st = smb + PH2_B + (uint32_t)s * TILEB;
#pragma unroll
        for (int i = 0; i < 2; ++i)
            cpa(st + doffB2[i], pB2[i] + (size_t)(s * 32) * CAD);
        asm volatile("cp.async.commit_group;" ::: "memory");
    }

    // ---- softmax epilogue (register-resident) ----
    const int qr = lane >> 2, qc = (lane & 3) * 2;
    const float bs = biasp[0];
    float part[4][2];
#pragma unroll
    for (int mi = 0; mi < 4; ++mi)
#pragma unroll
        for (int p = 0; p < 2; ++p) part[mi][p] = 0.f;
#pragma unroll
    for (int mi = 0; mi < 4; ++mi)
#pragma unroll
        for (int nj = 0; nj < 4; ++nj) {
            int c0 = nw + nj * 8 + qc;
            float sla = sl[c0], slA = sl[c0 + 1];
            float mk0 = sk[c0], mk1 = sk[c0 + 1];
#pragma unroll
            for (int p = 0; p < 2; ++p) {
                int r = mw + mi * 16 + qr + p * 8;
                float lb = slb[r] + bs;
                float e0 = mk0 * __expf(tanhf(acc[mi][nj][2 * p] + sla + lb));
                float e1 = mk1 * __expf(tanhf(acc[mi][nj][2 * p + 1] + slA + lb));
                acc[mi][nj][2 * p]     = e0;
                acc[mi][nj][2 * p + 1] = e1;
                part[mi][p] += e0 + e1;
            }
        }
#pragma unroll
    for (int mi = 0; mi < 4; ++mi)
#pragma unroll
        for (int p = 0; p < 2; ++p) {
            part[mi][p] += __shfl_xor_sync(0xffffffffu, part[mi][p], 1);
            part[mi][p] += __shfl_xor_sync(0xffffffffu, part[mi][p], 2);
        }
    if ((lane & 3) == 0) {
#pragma unroll
        for (int mi = 0; mi < 4; ++mi)
#pragma unroll
            for (int p = 0; p < 2; ++p) {
                int r = mw + mi * 16 + qr + p * 8;
                red[r * 4 + (w >> 1)] = part[mi][p];
            }
    }
    __syncthreads();
#pragma unroll
    for (int mi = 0; mi < 4; ++mi)
#pragma unroll
        for (int p = 0; p < 2; ++p) {
            int r = mw + mi * 16 + qr + p * 8;
            float4 rv = *(float4*)&red[r * 4];
            float inv = 1.0f / (rv.x + rv.y + rv.z + rv.w + 1e-30f);
#pragma unroll
            for (int nj = 0; nj < 4; ++nj) {
                uint32_t addr = smb + PH2_ATT + (uint32_t)(nw >> 5) * TILEB
                              + swz(r, nj) + qc * 2;
                uint32_t pk = pack2h(acc[mi][nj][2 * p] * inv,
                                     acc[mi][nj][2 * p + 1] * inv);
                asm volatile("st.shared.b32 [%0], %1;" :: "r"(addr), "r"(pk)
                             : "memory");
            }
        }

    // ---------------- phase 2: out = attn @ AOh (B trans) ----------------
    float acc2[4][4][4];
#pragma unroll
    for (int a = 0; a < 4; ++a)
#pragma unroll
        for (int bb = 0; bb < 4; ++bb)
#pragma unroll
            for (int cc = 0; cc < 4; ++cc) acc2[a][bb][cc] = 0.f;

    uint32_t stg2 = 0;
    for (int idx = 0; idx < 16; ++idx) {
        if (idx == 15) asm volatile("cp.async.wait_group 0;" ::: "memory");
        else           asm volatile("cp.async.wait_group 1;" ::: "memory");
        __syncthreads();
        if (idx + 2 < 16) {
            uint32_t s2 = stg2 + 2; if (s2 >= 3) s2 -= 3;
            const uint32_t st2 = smb + PH2_B + s2 * TILEB;
            const int nidx = idx + 2;
            const size_t boff = (size_t)((nidx & 3) * 32) * CAD + (nidx >> 2) * 128;
#pragma unroll
            for (int i = 0; i < 2; ++i)
                cpa(st2 + doffB2[i], pB2[i] + boff);
            asm volatile("cp.async.commit_group;" ::: "memory");
        }
        const uint32_t stB = smb + PH2_B + stg2 * TILEB;
        const uint32_t stA = smb + PH2_ATT + (uint32_t)(idx & 3) * TILEB;
#pragma unroll
        for (int ks = 0; ks < 2; ++ks) {
            const int cu = 2 * ks + cgrp;
            const int browk = 16 * ks + rin + ((grp >> 1) << 3);
            uint32_t bt[2][4];
#pragma unroll
            for (int j = 0; j < 2; ++j) {
                const int bc = (nw >> 3) + 2 * j + (grp & 1);
                ldsm4t(bt[j], stB + swzbt(browk, bc));
            }
            uint32_t a2[2][4];
            ldsm4(a2[0], stA + swz(rowm[0], cu));
#pragma unroll
            for (int mi = 0; mi < 4; ++mi) {
                const int cur = mi & 1;
                if (mi < 3) ldsm4(a2[cur ^ 1], stA + swz(rowm[mi + 1], cu));
#pragma unroll
                for (int nj = 0; nj < 4; ++nj) {
                    const int j = nj >> 1, o = nj & 1;
                    mma_f16(acc2[mi][nj], a2[cur], bt[j][o], bt[j][o + 2]);
                }
            }
        }
        if ((idx & 3) == 3) {
            const int v0 = (idx >> 2) * 128;
#pragma unroll
            for (int mi = 0; mi < 4; ++mi)
#pragma unroll
                for (int nj = 0; nj < 4; ++nj) {
                    size_t r0 = (size_t)b * CT + m0 + mw + mi * 16 + qr;
                    int gc = v0 + nw + nj * 8 + qc;
                    *(float2*)(OUT + r0 * CAD + gc) =
                        make_float2(acc2[mi][nj][0], acc2[mi][nj][1]);
                    *(float2*)(OUT + (r0 + 8) * CAD + gc) =
                        make_float2(acc2[mi][nj][2], acc2[mi][nj][3]);
                    acc2[mi][nj][0] = 0.f; acc2[mi][nj][1] = 0.f;
                    acc2[mi][nj][2] = 0.f; acc2[mi][nj][3] = 0.f;
                }
        }
        if (++stg2 == 3) stg2 = 0;
    }
}

// ---------------------------------------------------------------------------
extern "C" void kernel_launch(void* const* d_in, const int* in_sizes, int n_in,
                              void* d_out, int out_size) {
    const float* inputs = (const float*)d_in[0];
    const float* ao     = (const float*)d_in[1];
    const void*  mask   = d_in[2];
    const float* W      = (const float*)d_in[3];
    const float* a_w    = (const float*)d_in[4];
    const float* b_w    = (const float*)d_in[5];
    const float* bias   = (const float*)d_in[6];
    float* out = (float*)d_out;

    cudaFuncSetAttribute(g1x,     cudaFuncAttributeMaxDynamicSharedMemorySize, SMEM_G1);
    cudaFuncSetAttribute(g23_mma, cudaFuncAttributeMaxDynamicSharedMemorySize, SMEM_G23);

    pre_a<<<PA_LIN + PA_WT + 1, 256>>>(ao, a_w, W,
                                       (const unsigned char*)mask);   // 0
    g1x<<<dim3(20, 256), 256, SMEM_G1>>>(inputs, b_w);                // 1
    g23_mma<<<dim3(2, CB), 256, SMEM_G23>>>(bias, out);               // 2
}

// round 17
// speedup vs baseline: 1.1382x; 1.1382x over previous
#include <cuda_runtime.h>
#include <cuda_fp16.h>
#include <cstdint>

// ---------------------------------------------------------------------------
// GeneralizedBilinearAttention via mma.sync fp16 (base sm_103 ISA).
//   pre_a: AO rows (lina + AOh fp16, 8 rows/warp) + W->WTh + mask
//   g1x  : aM = AOh @ WTh^T (64x128 tiles, 1 product) + co-scheduled IN rows
//   g23  : sim = INh @ aMh^T (1 product) -> tanh/masked-softmax -> attn(smem)
//          -> out = attn @ AOh (B via ldmatrix.trans), fully fused
// fp32 acc. K32 chunks, 3-stage cp.async pipelines.
// (Round-14 configuration: measured best, 104.5us.)
// ---------------------------------------------------------------------------

#define CB 128
#define CT 256
#define CN 128
#define CAD 512
#define CVD 512

__device__ __align__(16) unsigned short g_AOh[CB * CN * CAD];
__device__ __align__(16) unsigned short g_INh[CB * CT * CVD];
__device__ __align__(16) unsigned short g_WTh[CVD * CAD];
__device__ __align__(16) unsigned short g_aMh[CB * CN * CVD];
__device__ __align__(16) float g_lina[CB * CN];
__device__ __align__(16) float g_linb[CB * CT];
__device__ __align__(16) float g_maskf[CB * CN];

// ---- smem layouts -------------------------------------------------------------
#define TILEB 8192
// g1: A 64x32 (4KB) + B 128x32 (8KB)
#define G1_A   0
#define G1_B   4096
#define STAGE1 12288
#define SMEM_G1 (3 * STAGE1)
// g23 phase 1: A, Bh (8KB each) = 16KB/stage, 3 stages = 48KB
#define SM_T0 0
#define SM_T1 TILEB
#define STAGE2 (2 * TILEB)
// g23 phase 2 overlay: attn 4x8KB at 0, B stages at 32KB (3x8KB)
#define PH2_ATT 0
#define PH2_B   32768
#define SM_LIN  57344
#define SM_MSK (SM_LIN + 512)
#define SM_LNB (SM_MSK + 512)
#define SM_RED (SM_LNB + 512)
#define SMEM_G23 (SM_RED + 2048)     // 60928

__device__ __forceinline__ uint32_t smem_u32(const void* p) {
    return (uint32_t)__cvta_generic_to_shared(p);
}
__device__ __forceinline__ uint32_t swz(int row, int c16) {
    return (uint32_t)(row * 64 + ((c16 ^ ((row >> 1) & 3)) << 4));
}
__device__ __forceinline__ uint32_t swzbt(int row, int c16) {
    return (uint32_t)(row * 256 + ((c16 ^ (row & 7)) << 4));
}
__device__ __forceinline__ void ldsm4(uint32_t* r, uint32_t addr) {
    asm volatile("ldmatrix.sync.aligned.m8n8.x4.shared.b16 {%0,%1,%2,%3}, [%4];"
                 : "=r"(r[0]), "=r"(r[1]), "=r"(r[2]), "=r"(r[3]) : "r"(addr));
}
__device__ __forceinline__ void ldsm4t(uint32_t* r, uint32_t addr) {
    asm volatile("ldmatrix.sync.aligned.m8n8.x4.trans.shared.b16 {%0,%1,%2,%3}, [%4];"
                 : "=r"(r[0]), "=r"(r[1]), "=r"(r[2]), "=r"(r[3]) : "r"(addr));
}
__device__ __forceinline__ void mma_f16(float* c, const uint32_t* a,
                                        uint32_t b0, uint32_t b1) {
    asm volatile("mma.sync.aligned.m16n8k16.row.col.f32.f16.f16.f32 "
                 "{%0,%1,%2,%3}, {%4,%5,%6,%7}, {%8,%9}, {%0,%1,%2,%3};"
                 : "+f"(c[0]), "+f"(c[1]), "+f"(c[2]), "+f"(c[3])
                 : "r"(a[0]), "r"(a[1]), "r"(a[2]), "r"(a[3]), "r"(b0), "r"(b1));
}
__device__ __forceinline__ void cpa(uint32_t d, const void* g) {
    asm volatile("cp.async.cg.shared.global [%0], [%1], 16;"
                 :: "r"(d), "l"(g) : "memory");
}
__device__ __forceinline__ uint32_t pack2h(float x, float y) {
    __half2 h = __floats2half2_rn(x, y);
    return *(uint32_t*)&h;
}

// ---------------------------------------------------------------------------
// pre_a: AO rows [256 blks x 8 warps x 8-row loop] + W->WTh [256] + mask [1].
// (8-row serial loop per warp, default cached loads: measured best, 14.3us.)
// ---------------------------------------------------------------------------
#define PA_LIN 256
#define PA_WT  256
__global__ void __launch_bounds__(256) pre_a(
    const float* __restrict__ AO, const float* __restrict__ a_w,
    const float* __restrict__ W, const unsigned char* __restrict__ m) {
    const int bid = blockIdx.x;
    const int tid = threadIdx.x;
    if (bid < PA_LIN) {
        const int idx = bid * 8 + (tid >> 5);
        const int lane = tid & 31;
        for (int rr = 0; rr < 8; ++rr) {
            const int r = idx + rr * 2048;
            const float* row = AO + (size_t)r * CAD;
            uint2* dst = (uint2*)g_AOh + (size_t)r * 128;
            float s = 0.f;
#pragma unroll
            for (int k = 0; k < 512; k += 128) {
                int e = k + lane * 4;
                float4 x = *(const float4*)(row + e);
                float4 y = *(const float4*)(a_w + e);
                s += x.x * y.x + x.y * y.y + x.z * y.z + x.w * y.w;
                dst[e >> 2] = make_uint2(pack2h(x.x, x.y), pack2h(x.z, x.w));
            }
#pragma unroll
            for (int o = 16; o; o >>= 1) s += __shfl_xor_sync(0xffffffffu, s, o);
            if (lane == 0) g_lina[r] = s;
        }
    } else if (bid < PA_LIN + PA_WT) {
        __shared__ float t[32][33];
        const int idx = bid - PA_LIN;
        const int v0 = (idx & 15) * 32, a0 = (idx >> 4) * 32;
        const int tx = tid & 31, ty = tid >> 5;
        for (int i = ty; i < 32; i += 8)
            t[i][tx] = W[(size_t)(a0 + i) * CVD + v0 + tx];
        __syncthreads();
        for (int i = ty; i < 32; i += 8)
            g_WTh[(size_t)(v0 + i) * CAD + a0 + tx] =
                __half_as_ushort(__float2half_rn(t[tx][i]));
    } else {
        __shared__ int s_notbin, s_odd;
        if (tid == 0) { s_notbin = 0; s_odd = 0; }
        __syncthreads();
        int notbin = 0, odd = 0;
        for (int i = tid; i < CB * CN; i += 256) {
            unsigned char v = m[i];
            if (v > 1) notbin = 1;
            if ((i & 3) && v == 1) odd = 1;
        }
        if (notbin) atomicOr(&s_notbin, 1);
        if (odd)    atomicOr(&s_odd, 1);
        __syncthreads();
        const int md = s_notbin ? 2 : (s_odd ? 0 : 1);
        for (int i = tid; i < CB * CN; i += 256) {
            float v;
            if (md == 0)      v = (m[i] != 0) ? 1.f : 0.f;
            else if (md == 1) v = (((const int*)(const void*)m)[i] != 0) ? 1.f : 0.f;
            else              v = (((const float*)(const void*)m)[i] != 0.f) ? 1.f : 0.f;
            g_maskf[i] = v;
        }
    }
}

// ---------------------------------------------------------------------------
// g1x: grid (4+16, 256).
//   x <  4 : GEMM CTA — aM tile = AOh @ WTh^T (64x128, 1 product)
//   x >= 4 : IN-row CTA — linb + INh fp16 convert (1 row/warp)
// ---------------------------------------------------------------------------
__global__ void __launch_bounds__(256, 3) g1x(const float* __restrict__ IN,
                                              const float* __restrict__ b_w) {
    extern __shared__ char sm[];
    const int tid = threadIdx.x;
    if (blockIdx.x >= 4) {
        const int r = (((int)blockIdx.x - 4) + (int)blockIdx.y * 16) * 8 + (tid >> 5);
        const int lane = tid & 31;
        const float* row = IN + (size_t)r * CVD;
        uint2* dst = (uint2*)g_INh + (size_t)r * 128;
        float s = 0.f;
#pragma unroll
        for (int k = 0; k < 512; k += 128) {
            int e = k + lane * 4;
            float4 x = *(const float4*)(row + e);
            float4 y = *(const float4*)(b_w + e);
            s += x.x * y.x + x.y * y.y + x.z * y.z + x.w * y.w;
            dst[e >> 2] = make_uint2(pack2h(x.x, x.y), pack2h(x.z, x.w));
        }
#pragma unroll
        for (int o = 16; o; o >>= 1) s += __shfl_xor_sync(0xffffffffu, s, o);
        if (lane == 0) g_linb[r] = s;
        return;
    }

    const uint32_t smb = smem_u32(sm);
    const int lane = tid & 31, w = tid >> 5;
    const int n0 = blockIdx.x * 128;
    const size_t m0 = (size_t)blockIdx.y * 64;
    const int mw = (w & 1) * 32, nw = (w >> 1) * 32;
    const int grp = lane >> 3, rin = lane & 7;
    int rowm[2], rowb[2];
#pragma unroll
    for (int mi = 0; mi < 2; ++mi) rowm[mi] = mw + mi * 16 + rin + ((grp & 1) << 3);
#pragma unroll
    for (int j = 0; j < 2; ++j)    rowb[j] = nw + j * 16 + rin + ((grp & 1) << 3);
    const int cgrp = grp >> 1;

    float acc[2][4][4];
#pragma unroll
    for (int a = 0; a < 2; ++a)
#pragma unroll
        for (int b = 0; b < 4; ++b)
#pragma unroll
            for (int cc = 0; cc < 4; ++cc) acc[a][b][cc] = 0.f;

    const unsigned short* A = g_AOh + m0 * CAD;
    const unsigned short* B = g_WTh + (size_t)n0 * CAD;

    uint32_t doffA, doffB[2];
    const unsigned short *pA, *pB[2];
    {
        int rowA = tid >> 2, cA = tid & 3;
        doffA = swz(rowA, cA);
        pA = A + (size_t)rowA * CAD + cA * 8;
#pragma unroll
        for (int i = 0; i < 2; ++i) {
            int u = i * 256 + tid, row = u >> 2, c = u & 3;
            doffB[i] = swz(row, c);
            pB[i] = B + (size_t)row * CAD + c * 8;
        }
    }
#pragma unroll
    for (int s = 0; s < 2; ++s) {
        const uint32_t st = smb + (uint32_t)s * STAGE1;
        cpa(st + G1_A + doffA, pA); pA += 32;
#pragma unroll
        for (int i = 0; i < 2; ++i) {
            cpa(st + G1_B + doffB[i], pB[i]); pB[i] += 32;
        }
        asm volatile("cp.async.commit_group;" ::: "memory");
    }
    uint32_t stg = 0;
    const int nch = CAD >> 5;
    for (int c = 0; c < nch; ++c) {
        if (c == nch - 1) asm volatile("cp.async.wait_group 0;" ::: "memory");
        else              asm volatile("cp.async.wait_group 1;" ::: "memory");
        __syncthreads();
        if (c + 2 < nch) {
            uint32_t s2 = stg + 2; if (s2 >= 3) s2 -= 3;
            const uint32_t st2 = smb + s2 * STAGE1;
            cpa(st2 + G1_A + doffA, pA); pA += 32;
#pragma unroll
            for (int i = 0; i < 2; ++i) {
                cpa(st2 + G1_B + doffB[i], pB[i]); pB[i] += 32;
            }
            asm volatile("cp.async.commit_group;" ::: "memory");
        }
        const uint32_t st = smb + stg * STAGE1;
#pragma unroll
        for (int ks = 0; ks < 2; ++ks) {
            const int cu = 2 * ks + cgrp;
            uint32_t b0[4], b1[4], a0[4], a1[4];
            ldsm4(b0, st + G1_B + swz(rowb[0], cu));
            ldsm4(b1, st + G1_B + swz(rowb[1], cu));
            ldsm4(a0, st + G1_A + swz(rowm[0], cu));
            ldsm4(a1, st + G1_A + swz(rowm[1], cu));
#pragma unroll
            for (int nj = 0; nj < 4; ++nj) {
                const int o = nj & 1;
                const uint32_t* bb = (nj < 2) ? b0 : b1;
                mma_f16(acc[0][nj], a0, bb[o], bb[o + 2]);
                mma_f16(acc[1][nj], a1, bb[o], bb[o + 2]);
            }
        }
        if (++stg == 3) stg = 0;
    }

    const int qr = lane >> 2, qc = (lane & 3) * 2;
    uint32_t* ghi = (uint32_t*)g_aMh;
#pragma unroll
    for (int mi = 0; mi < 2; ++mi)
#pragma unroll
        for (int nj = 0; nj < 4; ++nj) {
            size_t r0 = m0 + mw + mi * 16 + qr;
            size_t cp = (size_t)(n0 + nw + nj * 8 + qc) >> 1;
            ghi[r0 * (CVD >> 1) + cp] =
                pack2h(acc[mi][nj][0], acc[mi][nj][1]);
            ghi[(r0 + 8) * (CVD >> 1) + cp] =
                pack2h(acc[mi][nj][2], acc[mi][nj][3]);
        }
}

// ---------------------------------------------------------------------------
// G23: sim = INh @ aMh^T (1 product) -> softmax -> attn(smem) -> out = attn @ AOh.
//      grid (2 Mtiles, B), 256 threads, 2 CTAs/SM.
// ---------------------------------------------------------------------------
__global__ void __launch_bounds__(256, 2) g23_mma(const float* __restrict__ biasp,
                                                  float* __restrict__ OUT) {
    extern __shared__ char sm[];
    const uint32_t smb = smem_u32(sm);
    const int tid = threadIdx.x;
    const int b = blockIdx.y;
    const int m0 = blockIdx.x * 128;
    float* sl  = (float*)(sm + SM_LIN);
    float* sk  = (float*)(sm + SM_MSK);
    float* slb = (float*)(sm + SM_LNB);
    float* red = (float*)(sm + SM_RED);
    if (tid < 128) {
        sl[tid]  = g_lina[b * CN + tid];
        sk[tid]  = g_maskf[b * CN + tid];
        slb[tid] = g_linb[b * CT + m0 + tid];
    }
    const int lane = tid & 31, w = tid >> 5;
    const int mw = (w & 1) * 64, nw = (w >> 1) * 32;
    const int grp = lane >> 3, rin = lane & 7;
    int rowm[4], rowb[2];
#pragma unroll
    for (int mi = 0; mi < 4; ++mi) rowm[mi] = mw + mi * 16 + rin + ((grp & 1) << 3);
#pragma unroll
    for (int j = 0; j < 2; ++j)    rowb[j] = nw + j * 16 + rin + ((grp & 1) << 3);
    const int cgrp = grp >> 1;

    float acc[4][4][4];
#pragma unroll
    for (int a = 0; a < 4; ++a)
#pragma unroll
        for (int bb = 0; bb < 4; ++bb)
#pragma unroll
            for (int cc = 0; cc < 4; ++cc) acc[a][bb][cc] = 0.f;

    // ---------------- phase 1: sim mainloop (1 product) ----------------
    const unsigned short* A  = g_INh + ((size_t)b * CT + m0) * CVD;
    const unsigned short* Bh = g_aMh + (size_t)b * CN * CVD;

    uint32_t doff[2];
    const unsigned short *pA[2], *pBh[2];
#pragma unroll
    for (int i = 0; i < 2; ++i) {
        int u = i * 256 + tid, row = u >> 2, c = u & 3;
        doff[i] = swz(row, c);
        pA[i]  = A  + (size_t)row * CVD + c * 8;
        pBh[i] = Bh + (size_t)row * CVD + c * 8;
    }
#pragma unroll
    for (int s = 0; s < 2; ++s) {
        const uint32_t st = smb + (uint32_t)s * STAGE2;
#pragma unroll
        for (int i = 0; i < 2; ++i) {
            cpa(st + SM_T0 + doff[i], pA[i]);
            cpa(st + SM_T1 + doff[i], pBh[i]);
            pA[i] += 32; pBh[i] += 32;
        }
        asm volatile("cp.async.commit_group;" ::: "memory");
    }
    uint32_t stg = 0;
    const int nch = CVD >> 5;
    for (int c = 0; c < nch; ++c) {
        if (c == nch - 1) asm volatile("cp.async.wait_group 0;" ::: "memory");
        else              asm volatile("cp.async.wait_group 1;" ::: "memory");
        __syncthreads();
        if (c + 2 < nch) {
            uint32_t s2 = stg + 2; if (s2 >= 3) s2 -= 3;
            const uint32_t st2 = smb + s2 * STAGE2;
#pragma unroll
            for (int i = 0; i < 2; ++i) {
                cpa(st2 + SM_T0 + doff[i], pA[i]);
                cpa(st2 + SM_T1 + doff[i], pBh[i]);
                pA[i] += 32; pBh[i] += 32;
            }
            asm volatile("cp.async.commit_group;" ::: "memory");
        }
        const uint32_t st = smb + stg * STAGE2;
#pragma unroll
        for (int ks = 0; ks < 2; ++ks) {
            const int cu = 2 * ks + cgrp;
            uint32_t bh[2][4];
#pragma unroll
            for (int j = 0; j < 2; ++j)
                ldsm4(bh[j], st + SM_T1 + swz(rowb[j], cu));
            uint32_t a2[2][4];
            ldsm4(a2[0], st + SM_T0 + swz(rowm[0], cu));
#pragma unroll
            for (int mi = 0; mi < 4; ++mi) {
                const int cur = mi & 1;
                if (mi < 3) ldsm4(a2[cur ^ 1], st + SM_T0 + swz(rowm[mi + 1], cu));
#pragma unroll
                for (int nj = 0; nj < 4; ++nj) {
                    const int j = nj >> 1, o = nj & 1;
                    mma_f16(acc[mi][nj], a2[cur], bh[j][o], bh[j][o + 2]);
                }
            }
        }
        if (++stg == 3) stg = 0;
    }
    __syncthreads();

    // ---- phase-2 B preloads (overlap with softmax epilogue) ----
    uint32_t doffB2[2];
    const unsigned short* pB2[2];
#pragma unroll
    for (int i = 0; i < 2; ++i) {
        int u = i * 256 + tid;
        int rowB = u >> 4, cB = u & 15;
        doffB2[i] = swzbt(rowB, cB);
        pB2[i] = g_AOh + (size_t)b * CN * CAD + (size_t)rowB * CAD + cB * 8;
    }
#pragma unroll
    for (int s = 0; s < 2; ++s) {
        const uint32_t st = smb + PH2_B + (uint32_t)s * TILEB;
#pragma unroll
        for (int i = 0; i < 2; ++i)
            cpa(st + doffB2[i], pB2[i] + (size_t)(s * 32) * CAD);
        asm volatile("cp.async.commit_group;" ::: "memory");
    }

    // ---- softmax epilogue (register-resident) ----
    const int qr = lane >> 2, qc = (lane & 3) * 2;
    const float bs = biasp[0];
    float part[4][2];
#pragma unroll
    for (int mi = 0; mi < 4; ++mi)
#pragma unroll
        for (int p = 0; p < 2; ++p) part[mi][p] = 0.f;
#pragma unroll
    for (int mi = 0; mi < 4; ++mi)
#pragma unroll
        for (int nj = 0; nj < 4; ++nj) {
            int c0 = nw + nj * 8 + qc;
            float sla = sl[c0], slA = sl[c0 + 1];
            float mk0 = sk[c0], mk1 = sk[c0 + 1];
#pragma unroll
            for (int p = 0; p < 2; ++p) {
                int r = mw + mi * 16 + qr + p * 8;
                float lb = slb[r] + bs;
                float e0 = mk0 * __expf(tanhf(acc[mi][nj][2 * p] + sla + lb));
                float e1 = mk1 * __expf(tanhf(acc[mi][nj][2 * p + 1] + slA + lb));
                acc[mi][nj][2 * p]     = e0;
                acc[mi][nj][2 * p + 1] = e1;
                part[mi][p] += e0 + e1;
            }
        }
#pragma unroll
    for (int mi = 0; mi < 4; ++mi)
#pragma unroll
        for (int p = 0; p < 2; ++p) {
            part[mi][p] += __shfl_xor_sync(0xffffffffu, part[mi][p], 1);
            part[mi][p] += __shfl_xor_sync(0xffffffffu, part[mi][p], 2);
        }
    if ((lane & 3) == 0) {
#pragma unroll
        for (int mi = 0; mi < 4; ++mi)
#pragma unroll
            for (int p = 0; p < 2; ++p) {
                int r = mw + mi * 16 + qr + p * 8;
                red[r * 4 + (w >> 1)] = part[mi][p];
            }
    }
    __syncthreads();
#pragma unroll
    for (int mi = 0; mi < 4; ++mi)
#pragma unroll
        for (int p = 0; p < 2; ++p) {
            int r = mw + mi * 16 + qr + p * 8;
            float4 rv = *(float4*)&red[r * 4];
            float inv = 1.0f / (rv.x + rv.y + rv.z + rv.w + 1e-30f);
#pragma unroll
            for (int nj = 0; nj < 4; ++nj) {
                uint32_t addr = smb + PH2_ATT + (uint32_t)(nw >> 5) * TILEB
                              + swz(r, nj) + qc * 2;
                uint32_t pk = pack2h(acc[mi][nj][2 * p] * inv,
                                     acc[mi][nj][2 * p + 1] * inv);
                asm volatile("st.shared.b32 [%0], %1;" :: "r"(addr), "r"(pk)
                             : "memory");
            }
        }

    // ---------------- phase 2: out = attn @ AOh (B trans) ----------------
    float acc2[4][4][4];
#pragma unroll
    for (int a = 0; a < 4; ++a)
#pragma unroll
        for (int bb = 0; bb < 4; ++bb)
#pragma unroll
            for (int cc = 0; cc < 4; ++cc) acc2[a][bb][cc] = 0.f;

    uint32_t stg2 = 0;
    for (int idx = 0; idx < 16; ++idx) {
        if (idx == 15) asm volatile("cp.async.wait_group 0;" ::: "memory");
        else           asm volatile("cp.async.wait_group 1;" ::: "memory");
        __syncthreads();
        if (idx + 2 < 16) {
            uint32_t s2 = stg2 + 2; if (s2 >= 3) s2 -= 3;
            const uint32_t st2 = smb + PH2_B + s2 * TILEB;
            const int nidx = idx + 2;
            const size_t boff = (size_t)((nidx & 3) * 32) * CAD + (nidx >> 2) * 128;
#pragma unroll
            for (int i = 0; i < 2; ++i)
                cpa(st2 + doffB2[i], pB2[i] + boff);
            asm volatile("cp.async.commit_group;" ::: "memory");
        }
        const uint32_t stB = smb + PH2_B + stg2 * TILEB;
        const uint32_t stA = smb + PH2_ATT + (uint32_t)(idx & 3) * TILEB;
#pragma unroll
        for (int ks = 0; ks < 2; ++ks) {
            const int cu = 2 * ks + cgrp;
            const int browk = 16 * ks + rin + ((grp >> 1) << 3);
            uint32_t bt[2][4];
#pragma unroll
            for (int j = 0; j < 2; ++j) {
                const int bc = (nw >> 3) + 2 * j + (grp & 1);
                ldsm4t(bt[j], stB + swzbt(browk, bc));
            }
            uint32_t a2[2][4];
            ldsm4(a2[0], stA + swz(rowm[0], cu));
#pragma unroll
            for (int mi = 0; mi < 4; ++mi) {
                const int cur = mi & 1;
                if (mi < 3) ldsm4(a2[cur ^ 1], stA + swz(rowm[mi + 1], cu));
#pragma unroll
                for (int nj = 0; nj < 4; ++nj) {
                    const int j = nj >> 1, o = nj & 1;
                    mma_f16(acc2[mi][nj], a2[cur], bt[j][o], bt[j][o + 2]);
                }
            }
        }
        if ((idx & 3) == 3) {
            const int v0 = (idx >> 2) * 128;
#pragma unroll
            for (int mi = 0; mi < 4; ++mi)
#pragma unroll
                for (int nj = 0; nj < 4; ++nj) {
                    size_t r0 = (size_t)b * CT + m0 + mw + mi * 16 + qr;
                    int gc = v0 + nw + nj * 8 + qc;
                    *(float2*)(OUT + r0 * CAD + gc) =
                        make_float2(acc2[mi][nj][0], acc2[mi][nj][1]);
                    *(float2*)(OUT + (r0 + 8) * CAD + gc) =
                        make_float2(acc2[mi][nj][2], acc2[mi][nj][3]);
                    acc2[mi][nj][0] = 0.f; acc2[mi][nj][1] = 0.f;
                    acc2[mi][nj][2] = 0.f; acc2[mi][nj][3] = 0.f;
                }
        }
        if (++stg2 == 3) stg2 = 0;
    }
}

// ---------------------------------------------------------------------------
extern "C" void kernel_launch(void* const* d_in, const int* in_sizes, int n_in,
                              void* d_out, int out_size) {
    const float* inputs = (const float*)d_in[0];
    const float* ao     = (const float*)d_in[1];
    const void*  mask   = d_in[2];
    const float* W      = (const float*)d_in[3];
    const float* a_w    = (const float*)d_in[4];
    const float* b_w    = (const float*)d_in[5];
    const float* bias   = (const float*)d_in[6];
    float* out = (float*)d_out;

    cudaFuncSetAttribute(g1x,     cudaFuncAttributeMaxDynamicSharedMemorySize, SMEM_G1);
    cudaFuncSetAttribute(g23_mma, cudaFuncAttributeMaxDynamicSharedMemorySize, SMEM_G23);

    pre_a<<<PA_LIN + PA_WT + 1, 256>>>(ao, a_w, W,
                                       (const unsigned char*)mask);   // 0
    g1x<<<dim3(20, 256), 256, SMEM_G1>>>(inputs, b_w);                // 1
    g23_mma<<<dim3(2, CB), 256, SMEM_G23>>>(bias, out);               // 2
}